// round 9
// baseline (speedup 1.0000x reference)
#include <cuda_runtime.h>
#include <cstddef>

// Problem constants (fixed shapes)
#define BTOT 16384   // b*n
#define FIN  2048
#define CIN  128
#define CFF  512
#define COUT 128
#define TPOS 16
#define BM   128     // rows of x per block
#define CH   64      // cff chunk per iteration
#define NTHREADS 512

// k-major shared layouts. Strides ≡ 12 (mod 32) floats:
//  - fragment LDS banks   = 12*qp + group      -> 32 distinct, conflict-free
//  - GELU store banks     = 24*qp + group      -> 32 distinct, conflict-free
//  - float4 staging along row: conflict-free, 16B-aligned (stride mult of 4)
#define SR_A  140    // sA  [CIN k][BM r]
#define SN_W1 76     // sW1 [CIN k][CH n]
#define SR_H  140    // sH  [CH k][BM r]
#define SN_W2 140    // sW2 [CH k][COUT o]
#define OS    132    // epilogue sOut [COUT o][BM r]  (banks 8*qp+g, conflict-free)

#define SMEM_FLOATS (CIN*SR_A + CIN*SN_W1 + CH*SR_H + CH*SN_W2)
#define SMEM_BYTES  (SMEM_FLOATS * 4)   // 182,272 B -> 1 CTA/SM

// Scratch (device globals: allocation-free rule)
__device__ float g_xT [2048ull * 16384];   // xT[f][row],  f = c*16+t
__device__ float g_yT [2048ull * 16384];   // yT[f][row],  f = o*16+t
__device__ float g_w1t[2048 * 512];        // w1t[(c*16+t)][o]
__device__ float g_w2t[8192 * 128];        // w2t[(k*16+t)][o]

__device__ __forceinline__ float tf32r(float x) {
    unsigned r;
    asm("cvt.rna.tf32.f32 %0, %1;" : "=r"(r) : "f"(x));
    return __uint_as_float(r);
}

__device__ __forceinline__ float gelu_exact(float v) {
    return 0.5f * v * (1.0f + erff(v * 0.70710678118654752440f));
}

__device__ __forceinline__ void mma_tf32(float c[4], const unsigned a[4],
                                         unsigned b0, unsigned b1) {
    asm volatile(
        "mma.sync.aligned.m16n8k8.row.col.f32.tf32.tf32.f32 "
        "{%0,%1,%2,%3}, {%4,%5,%6,%7}, {%8,%9}, {%0,%1,%2,%3};\n"
        : "+f"(c[0]), "+f"(c[1]), "+f"(c[2]), "+f"(c[3])
        : "r"(a[0]), "r"(a[1]), "r"(a[2]), "r"(a[3]), "r"(b0), "r"(b1));
}

// ---------------- Generic tiled transpose: out[C][R] = in[R][C]^T -------------
__global__ void transpose_kernel(float* __restrict__ out, const float* __restrict__ in,
                                 int R, int C) {
    __shared__ float tile[32][33];
    const int bx = blockIdx.x * 32;   // C offset
    const int by = blockIdx.y * 32;   // R offset
    const int x  = threadIdx.x & 31;
    const int y0 = threadIdx.x >> 5;  // 0..7
#pragma unroll
    for (int j = 0; j < 32; j += 8) {
        const int r = by + y0 + j, c = bx + x;
        if (r < R && c < C) tile[y0 + j][x] = in[(size_t)r * C + c];
    }
    __syncthreads();
#pragma unroll
    for (int j = 0; j < 32; j += 8) {
        const int c = bx + y0 + j, r = by + x;
        if (c < C && r < R) out[(size_t)c * R + r] = tile[x][y0 + j];
    }
}

// ------------------------------- Main fused kernel ----------------------------
__global__ void __launch_bounds__(NTHREADS, 1)
jff_fused_kernel(const float* __restrict__ xT,
                 const float* __restrict__ w1t,
                 const float* __restrict__ w2t,
                 float* __restrict__ yT)
{
    extern __shared__ float smem[];
    float* sA  = smem;                   // [CIN][SR_A]
    float* sW1 = sA  + CIN * SR_A;       // [CIN][SN_W1]
    float* sH  = sW1 + CIN * SN_W1;      // [CH][SR_H]
    float* sW2 = sH  + CH  * SR_H;       // [CH][SN_W2]

    const int t   = blockIdx.x;          // t fastest -> L2 reuse across t
    const int m0  = blockIdx.y * BM;
    const int tid = threadIdx.x;
    const int warp  = tid >> 5;
    const int lane  = tid & 31;
    const int group = lane >> 2;         // 0..7
    const int qp    = lane & 3;          // 0..3
    const int wm = warp & 3;             // 4 warps along M (32 rows each)
    const int wn = warp >> 2;            // 4 warps along N

    // ---- Stage A tile: xT[f][row] -> sA[c][r], float4 coalesced both sides ----
    for (int idx = tid; idx < CIN * (BM / 4); idx += NTHREADS) {
        const int c  = idx >> 5;         // 0..127
        const int rq = idx & 31;
        float4 v = *(const float4*)&xT[(size_t)(c * TPOS + t) * BTOT + m0 + 4 * rq];
        v.x = tf32r(v.x); v.y = tf32r(v.y); v.z = tf32r(v.z); v.w = tf32r(v.w);
        *(float4*)&sA[c * SR_A + 4 * rq] = v;
    }

    // Persistent GEMM2 accumulators: [2 m][4 n][4] = 32 f32/thread
    float acc[2][4][4];
#pragma unroll
    for (int mi = 0; mi < 2; mi++)
#pragma unroll
        for (int ni = 0; ni < 4; ni++)
#pragma unroll
            for (int j = 0; j < 4; j++) acc[mi][ni][j] = 0.0f;

#pragma unroll 1
    for (int ch = 0; ch < CFF / CH; ch++) {
        const int n0 = ch * CH;

        __syncthreads();   // prior GEMM2 done reading sH/sW2; sA ready (iter 0)

        // ---- Stage W1 chunk: w1t[(c,t)][o] -> sW1[c][n], coalesced ----
        for (int idx = tid; idx < CIN * (CH / 4); idx += NTHREADS) {
            const int c  = idx >> 4;     // 0..127
            const int oq = idx & 15;
            float4 v = *(const float4*)&w1t[(size_t)(c * TPOS + t) * CFF + n0 + 4 * oq];
            v.x = tf32r(v.x); v.y = tf32r(v.y); v.z = tf32r(v.z); v.w = tf32r(v.w);
            *(float4*)&sW1[c * SN_W1 + 4 * oq] = v;
        }
        // ---- Stage W2 chunk: w2t[(k,t)][o] -> sW2[k][o], coalesced ----
        for (int idx = tid; idx < CH * (COUT / 4); idx += NTHREADS) {
            const int k  = idx >> 5;     // 0..63
            const int oq = idx & 31;
            float4 v = *(const float4*)&w2t[(size_t)((n0 + k) * TPOS + t) * COUT + 4 * oq];
            v.x = tf32r(v.x); v.y = tf32r(v.y); v.z = tf32r(v.z); v.w = tf32r(v.w);
            *(float4*)&sW2[k * SN_W2 + 4 * oq] = v;
        }
        __syncthreads();

        // ---- GEMM1: C1[32M x 16N] per warp = A * W1^T ----
        float c1[2][2][4];
#pragma unroll
        for (int mi = 0; mi < 2; mi++)
#pragma unroll
            for (int ni = 0; ni < 2; ni++)
#pragma unroll
                for (int j = 0; j < 4; j++) c1[mi][ni][j] = 0.0f;

#pragma unroll
        for (int ks = 0; ks < CIN / 8; ks++) {
            const int kb = ks * 8;
            unsigned a[2][4];
#pragma unroll
            for (int mi = 0; mi < 2; mi++) {
                const int r = wm * 32 + mi * 16 + group;
                a[mi][0] = __float_as_uint(sA[(kb + qp) * SR_A + r]);
                a[mi][1] = __float_as_uint(sA[(kb + qp) * SR_A + r + 8]);
                a[mi][2] = __float_as_uint(sA[(kb + qp + 4) * SR_A + r]);
                a[mi][3] = __float_as_uint(sA[(kb + qp + 4) * SR_A + r + 8]);
            }
#pragma unroll
            for (int ni = 0; ni < 2; ni++) {
                const int n = wn * 16 + ni * 8 + group;
                const unsigned b0 = __float_as_uint(sW1[(kb + qp) * SN_W1 + n]);
                const unsigned b1 = __float_as_uint(sW1[(kb + qp + 4) * SN_W1 + n]);
#pragma unroll
                for (int mi = 0; mi < 2; mi++) mma_tf32(c1[mi][ni], a[mi], b0, b1);
            }
        }

        // ---- exact GELU -> sH[n][r]  (n becomes k of GEMM2), conflict-free ----
#pragma unroll
        for (int mi = 0; mi < 2; mi++) {
            const int r0 = wm * 32 + mi * 16 + group;
#pragma unroll
            for (int ni = 0; ni < 2; ni++) {
                const int nb = wn * 16 + ni * 8 + 2 * qp;
                sH[nb * SR_H + r0]           = tf32r(gelu_exact(c1[mi][ni][0]));
                sH[(nb + 1) * SR_H + r0]     = tf32r(gelu_exact(c1[mi][ni][1]));
                sH[nb * SR_H + r0 + 8]       = tf32r(gelu_exact(c1[mi][ni][2]));
                sH[(nb + 1) * SR_H + r0 + 8] = tf32r(gelu_exact(c1[mi][ni][3]));
            }
        }
        __syncthreads();

        // ---- GEMM2: acc[32M x 32N] per warp += H * W2^T ----
#pragma unroll
        for (int ks = 0; ks < CH / 8; ks++) {
            const int kb = ks * 8;
            unsigned a[2][4];
#pragma unroll
            for (int mi = 0; mi < 2; mi++) {
                const int r = wm * 32 + mi * 16 + group;
                a[mi][0] = __float_as_uint(sH[(kb + qp) * SR_H + r]);
                a[mi][1] = __float_as_uint(sH[(kb + qp) * SR_H + r + 8]);
                a[mi][2] = __float_as_uint(sH[(kb + qp + 4) * SR_H + r]);
                a[mi][3] = __float_as_uint(sH[(kb + qp + 4) * SR_H + r + 8]);
            }
#pragma unroll
            for (int ni = 0; ni < 4; ni++) {
                const int o = wn * 32 + ni * 8 + group;
                const unsigned b0 = __float_as_uint(sW2[(kb + qp) * SN_W2 + o]);
                const unsigned b1 = __float_as_uint(sW2[(kb + qp + 4) * SN_W2 + o]);
#pragma unroll
                for (int mi = 0; mi < 2; mi++) mma_tf32(acc[mi][ni], a[mi], b0, b1);
            }
        }
    }

    // ---- Epilogue: regs -> smem [o][r] (conflict-free) -> coalesced yT stores ----
    __syncthreads();
    float* sO = smem;   // reuse sA region: 128*132 = 16896 floats, fits
#pragma unroll
    for (int mi = 0; mi < 2; mi++) {
        const int r0 = wm * 32 + mi * 16 + group;
#pragma unroll
        for (int ni = 0; ni < 4; ni++) {
            const int o0 = wn * 32 + ni * 8 + 2 * qp;
            sO[o0 * OS + r0]           = acc[mi][ni][0];
            sO[(o0 + 1) * OS + r0]     = acc[mi][ni][1];
            sO[o0 * OS + r0 + 8]       = acc[mi][ni][2];
            sO[(o0 + 1) * OS + r0 + 8] = acc[mi][ni][3];
        }
    }
    __syncthreads();
    for (int idx = tid; idx < COUT * (BM / 4); idx += NTHREADS) {
        const int o  = idx >> 5;
        const int rq = idx & 31;
        const float4 v = *(const float4*)&sO[o * OS + 4 * rq];
        *(float4*)&yT[(size_t)(o * TPOS + t) * BTOT + m0 + 4 * rq] = v;
    }
}

extern "C" void kernel_launch(void* const* d_in, const int* in_sizes, int n_in,
                              void* d_out, int out_size)
{
    const float* x  = (const float*)d_in[0];   // [16384, 2048] fp32
    const float* w1 = (const float*)d_in[1];   // [512,128,16]  fp32
    const float* w2 = (const float*)d_in[2];   // [128,512,16]  fp32
    float* y = (float*)d_out;                  // [16384, 2048] fp32
    (void)in_sizes; (void)n_in; (void)out_size;

    float *xT, *yT, *w1t, *w2t;
    cudaGetSymbolAddress((void**)&xT,  g_xT);
    cudaGetSymbolAddress((void**)&yT,  g_yT);
    cudaGetSymbolAddress((void**)&w1t, g_w1t);
    cudaGetSymbolAddress((void**)&w2t, g_w2t);

    cudaFuncSetAttribute(jff_fused_kernel,
                         cudaFuncAttributeMaxDynamicSharedMemorySize, SMEM_BYTES);

    // 1) Layout transforms (coalesced tiled transposes)
    transpose_kernel<<<dim3(FIN / 32, BTOT / 32), 256>>>(xT, x, BTOT, FIN);         // x  -> xT[f][row]
    transpose_kernel<<<dim3(2048 / 32, 512 / 32), 256>>>(w1t, w1, CFF, CIN * TPOS); // w1 -> [(c,t)][o]
    transpose_kernel<<<dim3(8192 / 32, 128 / 32), 256>>>(w2t, w2, COUT, CFF * TPOS);// w2 -> [(k,t)][o]

    // 2) Fused locally-connected FFN (writes yT[f][row])
    dim3 grid(TPOS, BTOT / BM);
    jff_fused_kernel<<<grid, NTHREADS, SMEM_BYTES>>>(xT, w1t, w2t, yT);

    // 3) yT -> y
    transpose_kernel<<<dim3(BTOT / 32, FIN / 32), 256>>>(y, yT, FIN, BTOT);
}

// round 11
// speedup vs baseline: 1.8006x; 1.8006x over previous
#include <cuda_runtime.h>
#include <cstdint>
#include <cstddef>

// ---------------- Problem constants ----------------
#define BTOT 16384   // b*n
#define FIN  2048
#define CIN  128
#define CFF  512
#define COUT 128
#define TPOS 16
#define BM   128
#define CH   64
#define NCHUNK 8
#define NTH  512

// ---------------- SMEM float offsets (XOR-swizzled, no padding) ----------------
// sA   [k=128][r=128]          @ 0       (16384 fl)
// sW1  [2][k=128][n=64]        @ 16384   (2 x 8192)
// sH   [k=64][r=128]           @ 32768   (8192)
// sW2  [k=64][o=128]           @ 40960   (8192)
#define SA_OFF   0
#define SW1_OFF  16384
#define SH_OFF   32768
#define SW2_OFF  40960
#define SMEM_FLOATS 49152
#define SMEM_BYTES (SMEM_FLOATS * 4)   // 196608 B
#define OS 132                          // epilogue sOut [o][r] stride (overlay @0)

// Named barriers
#define BAR_P  1   // sH produced (G1 arrive, G2 sync)
#define BAR_C  2   // sH consumed (G2 arrive, G1 sync)
#define BAR_G1 3
#define BAR_G2 4

#define BARN(id, cnt)  asm volatile("bar.sync %0, %1;"   :: "r"(id), "r"(cnt) : "memory")
#define BARA(id, cnt)  asm volatile("bar.arrive %0, %1;" :: "r"(id), "r"(cnt) : "memory")

#define CP_ASYNC16(saddr, gptr) \
    asm volatile("cp.async.cg.shared.global [%0], [%1], 16;" :: "r"(saddr), "l"(gptr) : "memory")
#define CP_COMMIT() asm volatile("cp.async.commit_group;" ::: "memory")
#define CP_WAIT(n)  asm volatile("cp.async.wait_group %0;" :: "n"(n) : "memory")

// ---------------- Scratch (allocation-free rule) ----------------
__device__ float g_xT [2048ull * 16384];   // xT[f][row], f = c*16+t  (tf32-rounded)
__device__ float g_yT [2048ull * 16384];   // yT[f][row], f = o*16+t
__device__ float g_w1t[2048 * 512];        // w1t[(c*16+t)][o]        (tf32-rounded)
__device__ float g_w2t[8192 * 128];        // w2t[(k*16+t)][o]        (tf32-rounded)

__device__ __forceinline__ uint32_t smem_u32(const void* p) {
    uint32_t a;
    asm("{ .reg .u64 t; cvta.to.shared.u64 t, %1; cvt.u32.u64 %0, t; }" : "=r"(a) : "l"(p));
    return a;
}
__device__ __forceinline__ float tf32r(float x) {
    unsigned r;
    asm("cvt.rna.tf32.f32 %0, %1;" : "=r"(r) : "f"(x));
    return __uint_as_float(r);
}
__device__ __forceinline__ float gelu_exact(float v) {
    return 0.5f * v * (1.0f + erff(v * 0.70710678118654752440f));
}
__device__ __forceinline__ void mma_tf32(float c[4], const unsigned a[4],
                                         unsigned b0, unsigned b1) {
    asm volatile(
        "mma.sync.aligned.m16n8k8.row.col.f32.tf32.tf32.f32 "
        "{%0,%1,%2,%3}, {%4,%5,%6,%7}, {%8,%9}, {%0,%1,%2,%3};\n"
        : "+f"(c[0]), "+f"(c[1]), "+f"(c[2]), "+f"(c[3])
        : "r"(a[0]), "r"(a[1]), "r"(a[2]), "r"(a[3]), "r"(b0), "r"(b1));
}

// ------------- Tiled transpose (+ optional tf32-RNA rounding): out[C][R] = in^T -------------
__global__ void transpose_kernel(float* __restrict__ out, const float* __restrict__ in,
                                 int R, int C, int doRound) {
    __shared__ float tile[32][33];
    const int bx = blockIdx.x * 32, by = blockIdx.y * 32;
    const int x = threadIdx.x & 31, y0 = threadIdx.x >> 5;
#pragma unroll
    for (int j = 0; j < 32; j += 8) {
        const int r = by + y0 + j, c = bx + x;
        if (r < R && c < C) {
            float v = in[(size_t)r * C + c];
            tile[y0 + j][x] = doRound ? tf32r(v) : v;
        }
    }
    __syncthreads();
#pragma unroll
    for (int j = 0; j < 32; j += 8) {
        const int c = bx + y0 + j, r = by + x;
        if (c < C && r < R) out[(size_t)c * R + r] = tile[x][y0 + j];
    }
}

// ------------------------------- Main warp-specialized kernel ----------------------------
__global__ void __launch_bounds__(NTH, 1)
jff_ws_kernel(const float* __restrict__ xT,
              const float* __restrict__ w1t,
              const float* __restrict__ w2t,
              float* __restrict__ yT)
{
    extern __shared__ float smem[];
    float* sA  = smem + SA_OFF;
    float* sW1 = smem + SW1_OFF;     // 2 buffers of 8192
    float* sH  = smem + SH_OFF;
    float* sW2 = smem + SW2_OFF;
    const uint32_t sb = smem_u32(smem);

    const int t   = blockIdx.x;      // t fastest -> L2 reuse of xT across t
    const int m0  = blockIdx.y * BM;
    const int tid = threadIdx.x;
    const int lane = tid & 31;
    const int g  = lane >> 2;        // 0..7
    const int qp = lane & 3;         // 0..3
    const int sw = qp << 3;          // XOR-swizzle term (thread-constant)

    if (tid < 256) {
        // ================= G1: GEMM1 + GELU producer =================
        const int w  = tid >> 5;         // 0..7
        const int wm = w & 3;            // 32-row slice
        const int wn = w >> 2;           // 0..1: 32-n slice

        // -- stage A tile via cp.async: 4096 16B chunks, 16 per thread --
#pragma unroll
        for (int i = 0; i < 16; i++) {
            const int q = tid + 256 * i;
            const int k = q >> 5, rq = q & 31;
            const uint32_t dst = sb + (uint32_t)(SA_OFF + k * 128 + ((4 * rq) ^ ((k & 3) << 3))) * 4;
            CP_ASYNC16(dst, &xT[(size_t)(k * TPOS + t) * BTOT + m0 + 4 * rq]);
        }
        CP_COMMIT();                                        // group: A
        // -- pre-stage W1 chunk 0 and 1 --
#pragma unroll
        for (int b = 0; b < 2; b++) {
#pragma unroll
            for (int i = 0; i < 8; i++) {
                const int q = tid + 256 * i;
                const int k = q >> 4, nq = q & 15;
                const uint32_t dst = sb + (uint32_t)(SW1_OFF + b * 8192 + k * 64 +
                                                     ((4 * nq) ^ ((k & 3) << 3))) * 4;
                CP_ASYNC16(dst, &w1t[(size_t)(k * TPOS + t) * CFF + b * CH + 4 * nq]);
            }
            CP_COMMIT();                                    // groups: W1[0], W1[1]
        }

        // thread-constant swizzled row indices
        int ra[2][2], rb[4];
#pragma unroll
        for (int mi = 0; mi < 2; mi++)
#pragma unroll
            for (int h = 0; h < 2; h++)
                ra[mi][h] = (wm * 32 + mi * 16 + h * 8 + g) ^ sw;
#pragma unroll
        for (int ni = 0; ni < 4; ni++)
            rb[ni] = (wn * 32 + ni * 8 + g) ^ sw;
        const int swHe = ((2 * qp) & 3) << 3;
        const int swHo = ((2 * qp + 1) & 3) << 3;

#pragma unroll 1
        for (int ch = 0; ch < NCHUNK; ch++) {
            if (ch < 7) { CP_WAIT(1); } else { CP_WAIT(0); }
            BARN(BAR_G1, 256);                              // W1[ch&1] (and A) visible group-wide
            const float* W1b = sW1 + (ch & 1) * 8192;

            // ---- GEMM1: c1[32r x 32n] = A[.,128] * W1^T ----
            float c1[2][4][4];
#pragma unroll
            for (int mi = 0; mi < 2; mi++)
#pragma unroll
                for (int ni = 0; ni < 4; ni++)
#pragma unroll
                    for (int j = 0; j < 4; j++) c1[mi][ni][j] = 0.0f;

#pragma unroll
            for (int ks = 0; ks < 16; ks++) {
                const int kA = ks * 8 + qp;
                unsigned a[2][4];
#pragma unroll
                for (int mi = 0; mi < 2; mi++) {
                    a[mi][0] = __float_as_uint(sA[kA * 128 + ra[mi][0]]);
                    a[mi][1] = __float_as_uint(sA[kA * 128 + ra[mi][1]]);
                    a[mi][2] = __float_as_uint(sA[(kA + 4) * 128 + ra[mi][0]]);
                    a[mi][3] = __float_as_uint(sA[(kA + 4) * 128 + ra[mi][1]]);
                }
#pragma unroll
                for (int ni = 0; ni < 4; ni++) {
                    const unsigned b0 = __float_as_uint(W1b[kA * 64 + rb[ni]]);
                    const unsigned b1 = __float_as_uint(W1b[(kA + 4) * 64 + rb[ni]]);
#pragma unroll
                    for (int mi = 0; mi < 2; mi++) mma_tf32(c1[mi][ni], a[mi], b0, b1);
                }
            }
            BARN(BAR_G1, 256);                              // all G1 done reading W1[ch&1]
            if (ch < 6) {                                   // restage this buffer for ch+2
#pragma unroll
                for (int i = 0; i < 8; i++) {
                    const int q = tid + 256 * i;
                    const int k = q >> 4, nq = q & 15;
                    const uint32_t dst = sb + (uint32_t)(SW1_OFF + (ch & 1) * 8192 + k * 64 +
                                                         ((4 * nq) ^ ((k & 3) << 3))) * 4;
                    CP_ASYNC16(dst, &w1t[(size_t)(k * TPOS + t) * CFF + (ch + 2) * CH + 4 * nq]);
                }
                CP_COMMIT();
            }

            if (ch > 0) BARN(BAR_C, 512);                   // G2 done reading sH(ch-1)

            // ---- exact GELU -> tf32 -> sH[n][r] ----
#pragma unroll
            for (int mi = 0; mi < 2; mi++) {
                const int r0 = wm * 32 + mi * 16 + g;
#pragma unroll
                for (int ni = 0; ni < 4; ni++) {
                    const int ne = wn * 32 + ni * 8 + 2 * qp;
                    sH[ne * 128 + (r0 ^ swHe)]             = tf32r(gelu_exact(c1[mi][ni][0]));
                    sH[(ne + 1) * 128 + (r0 ^ swHo)]       = tf32r(gelu_exact(c1[mi][ni][1]));
                    sH[ne * 128 + ((r0 + 8) ^ swHe)]       = tf32r(gelu_exact(c1[mi][ni][2]));
                    sH[(ne + 1) * 128 + ((r0 + 8) ^ swHo)] = tf32r(gelu_exact(c1[mi][ni][3]));
                }
            }
            BARA(BAR_P, 512);                               // publish sH(ch)
        }
        BARN(BAR_C, 512);                                   // consume G2's final C arrival
    } else {
        // ================= G2: GEMM2 consumer =================
        const int u  = tid - 256;
        const int w  = u >> 5;           // 0..7
        const int wm = w & 3;            // 32-row slice
        const int wn = w >> 2;           // 0..1: 64-o slice

        // -- pre-stage W2 chunk 0 --
#pragma unroll
        for (int i = 0; i < 8; i++) {
            const int q = u + 256 * i;
            const int k = q >> 5, oq = q & 31;
            const uint32_t dst = sb + (uint32_t)(SW2_OFF + k * 128 + ((4 * oq) ^ ((k & 3) << 3))) * 4;
            CP_ASYNC16(dst, &w2t[(size_t)(k * TPOS + t) * COUT + 4 * oq]);
        }
        CP_COMMIT();

        int rh[2][2], ro[8];
#pragma unroll
        for (int mi = 0; mi < 2; mi++)
#pragma unroll
            for (int h = 0; h < 2; h++)
                rh[mi][h] = (wm * 32 + mi * 16 + h * 8 + g) ^ sw;
#pragma unroll
        for (int ni = 0; ni < 8; ni++)
            ro[ni] = (wn * 64 + ni * 8 + g) ^ sw;

        float acc[2][8][4];
#pragma unroll
        for (int mi = 0; mi < 2; mi++)
#pragma unroll
            for (int ni = 0; ni < 8; ni++)
#pragma unroll
                for (int j = 0; j < 4; j++) acc[mi][ni][j] = 0.0f;

#pragma unroll 1
        for (int ch = 0; ch < NCHUNK; ch++) {
            CP_WAIT(0);
            BARN(BAR_G2, 256);                              // W2(ch) visible group-wide
            BARN(BAR_P, 512);                               // sH(ch) produced

            // ---- GEMM2: acc[32r x 64o] += H * W2^T ----
#pragma unroll
            for (int ks = 0; ks < 8; ks++) {
                const int kA = ks * 8 + qp;
                unsigned a[2][4];
#pragma unroll
                for (int mi = 0; mi < 2; mi++) {
                    a[mi][0] = __float_as_uint(sH[kA * 128 + rh[mi][0]]);
                    a[mi][1] = __float_as_uint(sH[kA * 128 + rh[mi][1]]);
                    a[mi][2] = __float_as_uint(sH[(kA + 4) * 128 + rh[mi][0]]);
                    a[mi][3] = __float_as_uint(sH[(kA + 4) * 128 + rh[mi][1]]);
                }
#pragma unroll
                for (int ni = 0; ni < 8; ni++) {
                    const unsigned b0 = __float_as_uint(sW2[kA * 128 + ro[ni]]);
                    const unsigned b1 = __float_as_uint(sW2[(kA + 4) * 128 + ro[ni]]);
#pragma unroll
                    for (int mi = 0; mi < 2; mi++) mma_tf32(acc[mi][ni], a[mi], b0, b1);
                }
            }
            BARN(BAR_G2, 256);                              // all G2 done reading W2(ch)
            if (ch < 7) {                                   // restage W2 for ch+1
#pragma unroll
                for (int i = 0; i < 8; i++) {
                    const int q = u + 256 * i;
                    const int k = q >> 5, oq = q & 31;
                    const uint32_t dst = sb + (uint32_t)(SW2_OFF + k * 128 +
                                                         ((4 * oq) ^ ((k & 3) << 3))) * 4;
                    CP_ASYNC16(dst, &w2t[(size_t)((ch + 1) * CH * TPOS + k * TPOS + t) * COUT + 4 * oq]);
                }
                CP_COMMIT();
            }
            BARA(BAR_C, 512);                               // sH(ch) consumed
        }

        // ---- G2 writes acc -> sO[o][r] (overlay @0, conflict-free: banks 8qp+g) ----
        float* sO = smem;
#pragma unroll
        for (int mi = 0; mi < 2; mi++) {
            const int r0 = wm * 32 + mi * 16 + g;
#pragma unroll
            for (int ni = 0; ni < 8; ni++) {
                const int o0 = wn * 64 + ni * 8 + 2 * qp;
                sO[o0 * OS + r0]           = acc[mi][ni][0];
                sO[(o0 + 1) * OS + r0]     = acc[mi][ni][1];
                sO[o0 * OS + r0 + 8]       = acc[mi][ni][2];
                sO[(o0 + 1) * OS + r0 + 8] = acc[mi][ni][3];
            }
        }
    }

    __syncthreads();
    // ---- all 512 threads: coalesced yT stores ----
    {
        float* sO = smem;
#pragma unroll
        for (int i = 0; i < 8; i++) {
            const int idx = tid + NTH * i;                  // 4096 float4 slots
            const int o = idx >> 5, rq = idx & 31;
            const float4 v = *(const float4*)&sO[o * OS + 4 * rq];
            *(float4*)&yT[(size_t)(o * TPOS + t) * BTOT + m0 + 4 * rq] = v;
        }
    }
}

extern "C" void kernel_launch(void* const* d_in, const int* in_sizes, int n_in,
                              void* d_out, int out_size)
{
    const float* x  = (const float*)d_in[0];   // [16384, 2048] fp32
    const float* w1 = (const float*)d_in[1];   // [512,128,16]  fp32
    const float* w2 = (const float*)d_in[2];   // [128,512,16]  fp32
    float* y = (float*)d_out;                  // [16384, 2048] fp32
    (void)in_sizes; (void)n_in; (void)out_size;

    float *xT, *yT, *w1t, *w2t;
    cudaGetSymbolAddress((void**)&xT,  g_xT);
    cudaGetSymbolAddress((void**)&yT,  g_yT);
    cudaGetSymbolAddress((void**)&w1t, g_w1t);
    cudaGetSymbolAddress((void**)&w2t, g_w2t);

    cudaFuncSetAttribute(jff_ws_kernel,
                         cudaFuncAttributeMaxDynamicSharedMemorySize, SMEM_BYTES);

    // 1) Layout transforms with tf32-RNA rounding folded in (raw-byte cp.async later)
    transpose_kernel<<<dim3(FIN / 32, BTOT / 32), 256>>>(xT, x, BTOT, FIN, 1);
    transpose_kernel<<<dim3(2048 / 32, 512 / 32), 256>>>(w1t, w1, CFF, CIN * TPOS, 1);
    transpose_kernel<<<dim3(8192 / 32, 128 / 32), 256>>>(w2t, w2, COUT, CFF * TPOS, 1);

    // 2) Warp-specialized fused locally-connected FFN (writes yT[f][row])
    dim3 grid(TPOS, BTOT / BM);
    jff_ws_kernel<<<grid, NTH, SMEM_BYTES>>>(xT, w1t, w2t, yT);

    // 3) yT -> y (no rounding)
    transpose_kernel<<<dim3(BTOT / 32, FIN / 32), 256>>>(y, yT, FIN, BTOT, 0);
}